// round 2
// baseline (speedup 1.0000x reference)
#include <cuda_runtime.h>
#include <math.h>

#define HEAD_SIZE   128
#define NUM_Q       32
#define NUM_K       8
#define NUM_QK      (NUM_Q + NUM_K)          // 40 heads get norm+rope
#define ROW_ELEMS   (48 * HEAD_SIZE)         // 6144 floats per token
#define V_OFFSET    (NUM_QK * HEAD_SIZE)     // 5120
#define EPS         1e-6f

__global__ __launch_bounds__(256, 4)
void rope_qknorm_kernel(const float* __restrict__ qkv,
                        const float* __restrict__ q_weight,
                        const float* __restrict__ k_weight,
                        const int*   __restrict__ positions,
                        float* __restrict__ out)
{
    __shared__ float s_cos[64];
    __shared__ float s_sin[64];
    __shared__ float s_w[2][HEAD_SIZE];   // [0]=q_weight, [1]=k_weight

    const int t    = blockIdx.x;
    const int tid  = threadIdx.x;
    const int warp = tid >> 5;
    const int lane = tid & 31;

    // ---- per-token cos/sin table (64 rotary freqs) ----
    // Mirror the reference's f32 arithmetic EXACTLY:
    //   inv_freq = 1.0f / powf(10000.0f, (2j)/128.0f)   (XLA f32 pow == __nv_powf)
    //   arg      = (float)pos * inv_freq                (f32 multiply)
    //   cos/sin via libdevice cosf/sinf (== XLA __nv_cosf/__nv_sinf)
    if (tid < 64) {
        float e     = (float)(2 * tid) / 128.0f;
        float inv_f = 1.0f / powf(10000.0f, e);
        float pos_f = (float)positions[t];
        float arg   = pos_f * inv_f;
        s_cos[tid] = cosf(arg);
        s_sin[tid] = sinf(arg);
    }
    if (tid < HEAD_SIZE) {
        s_w[0][tid] = q_weight[tid];
        s_w[1][tid] = k_weight[tid];
    }
    __syncthreads();

    const float* __restrict__ row  = qkv + (size_t)t * ROW_ELEMS;
    float*       __restrict__ orow = out + (size_t)t * ROW_ELEMS;

    // ---- 40 heads, one warp per head, 5 heads/warp ----
    #pragma unroll
    for (int i = 0; i < 5; i++) {
        const int h = warp + i * 8;                 // 0..39
        const float* w  = s_w[h >= NUM_Q ? 1 : 0];
        const float* hp = row  + h * HEAD_SIZE;
        float*       op = orow + h * HEAD_SIZE;

        // lane-local elements: j, j+32 (first halves) and j+64, j+96 (second halves)
        float x0 = hp[lane];
        float x1 = hp[lane + 32];
        float x2 = hp[lane + 64];
        float x3 = hp[lane + 96];

        float ss = x0 * x0 + x1 * x1 + x2 * x2 + x3 * x3;
        #pragma unroll
        for (int o = 16; o; o >>= 1)
            ss += __shfl_xor_sync(0xffffffffu, ss, o);

        const float inv = rsqrtf(ss * (1.0f / HEAD_SIZE) + EPS);

        // match reference order: (x * inv) * w
        x0 = (x0 * inv) * w[lane];
        x1 = (x1 * inv) * w[lane + 32];
        x2 = (x2 * inv) * w[lane + 64];
        x3 = (x3 * inv) * w[lane + 96];

        const float c0 = s_cos[lane],      sn0 = s_sin[lane];
        const float c1 = s_cos[lane + 32], sn1 = s_sin[lane + 32];

        // NeoX rotate: pairs (j, j+64)
        op[lane]      = x0 * c0 - x2 * sn0;
        op[lane + 64] = x2 * c0 + x0 * sn0;
        op[lane + 32] = x1 * c1 - x3 * sn1;
        op[lane + 96] = x3 * c1 + x1 * sn1;
    }

    // ---- V passthrough: 1024 floats = 256 float4, one per thread ----
    const float4* __restrict__ v4 = (const float4*)(row  + V_OFFSET);
    float4*       __restrict__ o4 = (float4*)(orow + V_OFFSET);
    o4[tid] = v4[tid];
}

extern "C" void kernel_launch(void* const* d_in, const int* in_sizes, int n_in,
                              void* d_out, int out_size)
{
    const float* qkv       = (const float*)d_in[0];
    const float* q_weight  = (const float*)d_in[1];
    const float* k_weight  = (const float*)d_in[2];
    const int*   positions = (const int*)  d_in[3];
    float*       out       = (float*)d_out;

    const int T = in_sizes[3];   // 8192 tokens
    rope_qknorm_kernel<<<T, 256>>>(qkv, q_weight, k_weight, positions, out);
}